// round 16
// baseline (speedup 1.0000x reference)
#include <cuda_runtime.h>
#include <cuda_fp16.h>
#include <cuda_pipeline.h>
#include <mma.h>
#include <stdint.h>
#include <math.h>

using namespace nvcuda;

#define TOK 4096
#define DIM 2048
#define NH 16
#define NKVH 4
#define HD 128
#define FF 7168
#define SEQ 2048
#define BATCH 2
#define QKVN 3072
#define GUN (2 * FF)

#define GBM 128
#define GBN 128
#define GBK 64
#define GLD 72
#define TILE_ELEMS (GBM * GLD)
#define STAGE_BYTES (2 * TILE_ELEMS * 2)
#define GEMM_SMEM_BYTES (2 * STAGE_BYTES)

// attention smem (128-row q-tile): Qs fp16 [128][136], Ks/Vs fp16 [64][136],
// Ps f32 [128][72] (fp16 P aliased), rowm/rowl/rowsc[128]
#define ATTN_SMEM_BYTES (128 * 136 * 2 + 2 * 64 * 136 * 2 + 128 * 72 * 4 + 3 * 128 * 4)

// ---------------- scratch (static device globals; no allocation allowed) ---
__device__ float g_h[TOK * DIM];
__device__ int   g_idx[TOK];
__device__ float g_scale[TOK];
__device__ int   g_nsel;
__device__ float2 g_rope[SEQ * 64];

// fp16 activation planes
__device__ __half g_xnh[TOK * DIM];
__device__ __half g_qkvh[TOK * QKVN];
__device__ __half g_ah[TOK * DIM];
__device__ __half g_hnh[TOK * DIM];
__device__ __half g_acth[TOK * FF];
// fp16 weight planes
__device__ __half g_qkvw[QKVN * DIM];
__device__ __half g_owh[DIM * DIM];
__device__ __half g_guw[GUN * DIM];   // interleaved: row 2i = gate i, 2i+1 = up i
__device__ __half g_dwh[DIM * FF];

// ---------------- fp32 -> fp16 convert (16B/thread, proven) ----------------
__global__ void cvt_kernel(const float* __restrict__ src,
                           __half* __restrict__ dst, int n4) {
    int i = blockIdx.x * blockDim.x + threadIdx.x;
    if (i >= n4) return;
    float4 v = ((const float4*)src)[i];
    __half2* hp = (__half2*)dst + i * 2;
    hp[0] = __floats2half2_rn(v.x, v.y);
    hp[1] = __floats2half2_rn(v.z, v.w);
}

// ---------------- fp32 -> fp16 convert with row interleave 2r+off ----------
__global__ void cvt_ilv_kernel(const float* __restrict__ src,
                               __half* __restrict__ dst, int n4, int off) {
    int i = blockIdx.x * blockDim.x + threadIdx.x;
    if (i >= n4) return;
    float4 v = ((const float4*)src)[i];
    int idx = i * 4;
    int row = idx / DIM;
    int col = idx - row * DIM;
    __half2* hp = (__half2*)(dst + ((size_t)(2 * row + off)) * DIM + col);
    hp[0] = __floats2half2_rn(v.x, v.y);
    hp[1] = __floats2half2_rn(v.z, v.w);
}

// ---------------- fp16 GEMM: C[M,N] = A[M,K] @ W[N,K]^T --------------------
__global__ __launch_bounds__(256)
void fp16_gemm(const __half* __restrict__ Ah, const __half* __restrict__ Wh,
               float* __restrict__ C, __half* __restrict__ Ch,
               const float* __restrict__ Res,
               int M, int N, int K, int gather, int scatter, int dynm, int silu) {
    const int Mreal = dynm ? g_nsel : M;
    const int bm = blockIdx.y * GBM;
    if (bm >= Mreal) return;
    const int bn = blockIdx.x * GBN;

    extern __shared__ char smraw[];

    const int tid = threadIdx.x;
    const int warp = tid >> 5;
    const int wm = (warp >> 1) * 32;
    const int wn = (warp & 1) * 64;

    const int cc = tid & 7;
    int lrow[4], arowg[4], wrowg[4];
    bool avalid[4];
    for (int t = 0; t < 4; t++) {
        int row = (tid >> 3) + t * 32;
        lrow[t] = row;
        int am = bm + row;
        avalid[t] = (am < Mreal);
        arowg[t] = avalid[t] ? (gather ? g_idx[am] : am) : 0;
        wrowg[t] = bn + row;
    }

    wmma::fragment<wmma::accumulator, 16, 16, 16, float> acc[2][4];
    for (int mt = 0; mt < 2; mt++)
        for (int nt = 0; nt < 4; nt++)
            wmma::fill_fragment(acc[mt][nt], 0.0f);

    const int nchunks = K / GBK;
    const uint4 zz = make_uint4(0u, 0u, 0u, 0u);

    for (int c = 0; c < nchunks + 1; c++) {
        if (c < nchunks) {
            char* sb = smraw + (c & 1) * STAGE_BYTES;
            __half* sA = (__half*)sb;
            __half* sW = sA + TILE_ELEMS;
            int k0 = c * GBK;
            for (int t = 0; t < 4; t++) {
                int so = lrow[t] * GLD + cc * 8;
                if (avalid[t]) {
                    size_t go = (size_t)arowg[t] * K + k0 + cc * 8;
                    __pipeline_memcpy_async(sA + so, Ah + go, 16);
                } else {
                    *(uint4*)(sA + so) = zz;
                }
                size_t wo = (size_t)wrowg[t] * K + k0 + cc * 8;
                __pipeline_memcpy_async(sW + so, Wh + wo, 16);
            }
            __pipeline_commit();
        }
        if (c > 0) {
            __pipeline_wait_prior(c < nchunks ? 1 : 0);
            __syncthreads();
            char* sb = smraw + ((c - 1) & 1) * STAGE_BYTES;
            const __half* sA = (const __half*)sb;
            const __half* sW = sA + TILE_ELEMS;
            for (int kc = 0; kc < GBK; kc += 16) {
                wmma::fragment<wmma::matrix_a, 16, 16, 16, __half, wmma::row_major> af[2];
                wmma::fragment<wmma::matrix_b, 16, 16, 16, __half, wmma::col_major> bf[4];
                for (int mt = 0; mt < 2; mt++)
                    wmma::load_matrix_sync(af[mt], sA + (wm + mt * 16) * GLD + kc, GLD);
                for (int nt = 0; nt < 4; nt++)
                    wmma::load_matrix_sync(bf[nt], sW + (wn + nt * 16) * GLD + kc, GLD);
                for (int mt = 0; mt < 2; mt++)
                    for (int nt = 0; nt < 4; nt++)
                        wmma::mma_sync(acc[mt][nt], af[mt], bf[nt], acc[mt][nt]);
            }
            __syncthreads();
        }
    }

    float* Cs = (float*)smraw;     // 128 x 136
    for (int mt = 0; mt < 2; mt++)
        for (int nt = 0; nt < 4; nt++)
            wmma::store_matrix_sync(Cs + (wm + mt * 16) * 136 + wn + nt * 16,
                                    acc[mt][nt], 136, wmma::mem_row_major);
    __syncthreads();

    {
        int r = tid >> 1;
        int c0 = (tid & 1) * 64;
        int row = bm + r;
        if (row < Mreal) {
            const float* cr = Cs + r * 136 + c0;
            if (Ch) {
                if (silu) {
                    size_t off = (size_t)row * (N / 2) + (bn + c0) / 2;
                    for (int j0 = 0; j0 < 64; j0 += 16) {
                        __half tmp[8];
                        for (int j = 0; j < 8; j++) {
                            float g = cr[j0 + 2 * j];
                            float u = cr[j0 + 2 * j + 1];
                            tmp[j] = __float2half((g / (1.f + __expf(-g))) * u);
                        }
                        *(uint4*)(Ch + off + j0 / 2) = *(uint4*)tmp;
                    }
                } else {
                    size_t off = (size_t)row * N + bn + c0;
                    for (int j0 = 0; j0 < 64; j0 += 8) {
                        __half tmp[8];
                        for (int j = 0; j < 8; j++) tmp[j] = __float2half(cr[j0 + j]);
                        *(uint4*)(Ch + off + j0) = *(uint4*)tmp;
                    }
                }
            } else {
                int crow = scatter ? g_idx[row] : row;
                size_t off = (size_t)crow * N + bn + c0;
                if (scatter) {
                    float rs = g_scale[crow];
                    for (int j = 0; j < 64; j++) C[off + j] += rs * cr[j];
                } else if (Res) {
                    for (int j = 0; j < 64; j++) C[off + j] = Res[off + j] + cr[j];
                } else {
                    for (int j = 0; j < 64; j++) C[off + j] = cr[j];
                }
            }
        }
    }
}

// ---------------- RMSNorm (writes fp16 plane) -------------------------------
__global__ void rmsnorm_half_kernel(const float* __restrict__ x,
                                    const float* __restrict__ w,
                                    __half* __restrict__ oh) {
    const int row = blockIdx.x;
    const float* xr = x + (size_t)row * DIM;
    float ss = 0.f;
    for (int i = threadIdx.x; i < DIM; i += 256) {
        float v = xr[i];
        ss += v * v;
    }
    __shared__ float red[256];
    red[threadIdx.x] = ss;
    __syncthreads();
    for (int off = 128; off > 0; off >>= 1) {
        if (threadIdx.x < off) red[threadIdx.x] += red[threadIdx.x + off];
        __syncthreads();
    }
    float rs = rsqrtf(red[0] / (float)DIM + 1e-5f);
    for (int i = threadIdx.x; i < DIM; i += 256)
        oh[(size_t)row * DIM + i] = __float2half(xr[i] * rs * w[i]);
}

// ---------------- RoPE table (once per call; tiny) --------------------------
__global__ void rope_table_kernel(float2* __restrict__ tab) {
    int i = blockIdx.x * blockDim.x + threadIdx.x;
    if (i >= SEQ * 64) return;
    int pos = i >> 6, half = i & 63;
    float inv = expf(-logf(10000.f) * (float)half * (1.f / 64.f));
    float ang = (float)pos * inv;
    tab[i] = make_float2(cosf(ang), sinf(ang));
}

// ---------------- RoPE apply on fused qkv plane (Q heads + K heads) ---------
__global__ void rope_apply_kernel(__half* __restrict__ qkv,
                                  const float2* __restrict__ tab) {
    int i = blockIdx.x * blockDim.x + threadIdx.x;
    const int total = TOK * (NH + NKVH) * 64;
    if (i >= total) return;
    int half = i & 63;
    int t = i >> 6;
    int hd = t % (NH + NKVH);
    int tok = t / (NH + NKVH);
    int col = (hd < NH) ? hd * HD : DIM + (hd - NH) * HD;
    float2 cs = tab[(tok % SEQ) * 64 + half];
    __half* base = qkv + (size_t)tok * QKVN + col + half;
    float x1 = __half2float(base[0]), x2 = __half2float(base[64]);
    base[0] = __float2half(x1 * cs.x - x2 * cs.y);
    base[64] = __float2half(x2 * cs.x + x1 * cs.y);
}

// ---------------- WMMA flash attention, 128-row q-tiles ---------------------
// 512 threads / 16 warps: wq=warp>>1 (16-row band), wc=warp&1 (col half).
// O in register fragments; K/V tiles amortized over 128 q-rows.
__global__ __launch_bounds__(512)
void attn_wmma(const __half* __restrict__ QKV, __half* __restrict__ Om) {
    extern __shared__ char smb[];
    __half* Qs = (__half*)smb;               // [128][136]
    __half* Ks = Qs + 128 * 136;             // [64][136]
    __half* Vs = Ks + 64 * 136;              // [64][136]
    float*  Ps = (float*)(Vs + 64 * 136);    // [128][72] f32; fp16 P aliased
    __half* Ph = (__half*)Ps;
    float* rowm = Ps + 128 * 72;
    float* rowl = rowm + 128;
    float* rowsc = rowl + 128;

    const int tid = threadIdx.x;
    const int warp = tid >> 5;
    const int lane = tid & 31;
    const int wq = warp >> 1;      // 0..7
    const int wc = warp & 1;
    const int qt = gridDim.x - 1 - blockIdx.x;   // heavy tiles first
    const int h = blockIdx.y, b = blockIdx.z;
    const int kvh = h / (NH / NKVH);
    const int q0 = qt * 128;

    for (int i = tid; i < 128 * 16; i += 512) {
        int r = i >> 4, ch = i & 15;
        *(uint4*)(Qs + r * 136 + ch * 8) =
            *(const uint4*)(QKV + (size_t)(b * SEQ + q0 + r) * QKVN + h * HD + ch * 8);
    }
    if (tid < 128) { rowm[tid] = -1e30f; rowl[tid] = 0.f; }

    const float qk_scale = 0.08838834764831845f;

    wmma::fragment<wmma::accumulator, 16, 16, 16, float> ofr[4];
    for (int nt = 0; nt < 4; nt++) wmma::fill_fragment(ofr[nt], 0.0f);

    const int fr0 = wq * 16 + (lane >> 2);   // local row of elems 0,1,4,5
    const int fr1 = fr0 + 8;

    const int ktmax = 2 * qt + 1;
    for (int kt = 0; kt <= ktmax; kt++) {
        __syncthreads();
        for (int i = tid; i < 64 * 16; i += 512) {
            int r = i >> 4, ch = i & 15;
            size_t base = (size_t)(b * SEQ + kt * 64 + r) * QKVN + kvh * HD + ch * 8;
            *(uint4*)(Ks + r * 136 + ch * 8) = *(const uint4*)(QKV + base + DIM);
            *(uint4*)(Vs + r * 136 + ch * 8) = *(const uint4*)(QKV + base + DIM + NKVH * HD);
        }
        __syncthreads();

        // ---- S = Q @ K^T : each warp 16 rows x 32 cols ----
        {
            wmma::fragment<wmma::accumulator, 16, 16, 16, float> sfr[2];
            wmma::fill_fragment(sfr[0], 0.0f);
            wmma::fill_fragment(sfr[1], 0.0f);
            for (int kd = 0; kd < 128; kd += 16) {
                wmma::fragment<wmma::matrix_a, 16, 16, 16, __half, wmma::row_major> af;
                wmma::load_matrix_sync(af, Qs + wq * 16 * 136 + kd, 136);
                for (int nt = 0; nt < 2; nt++) {
                    wmma::fragment<wmma::matrix_b, 16, 16, 16, __half, wmma::col_major> bf;
                    wmma::load_matrix_sync(bf, Ks + (wc * 32 + nt * 16) * 136 + kd, 136);
                    wmma::mma_sync(sfr[nt], af, bf, sfr[nt]);
                }
            }
            for (int nt = 0; nt < 2; nt++)
                wmma::store_matrix_sync(Ps + wq * 16 * 72 + wc * 32 + nt * 16,
                                        sfr[nt], 72, wmma::mem_row_major);
        }
        __syncthreads();

        // ---- masked online softmax: 4 threads per row (128 rows) ----
        float pv[16];
        int r = tid >> 2, sub = tid & 3;
        {
            int gq = q0 + r;
            float m0 = rowm[r];
            float vals[16];
            float mx = m0;
            for (int c0 = 0; c0 < 16; c0++) {
                int c = sub * 16 + c0;
                int gk = kt * 64 + c;
                float v = Ps[r * 72 + c] * qk_scale;
                if (gk > gq) v = -1e30f;
                vals[c0] = v;
                mx = fmaxf(mx, v);
            }
            mx = fmaxf(mx, __shfl_xor_sync(0xffffffffu, mx, 1));
            mx = fmaxf(mx, __shfl_xor_sync(0xffffffffu, mx, 2));
            float sum = 0.f;
            for (int c0 = 0; c0 < 16; c0++) {
                pv[c0] = __expf(vals[c0] - mx);
                sum += pv[c0];
            }
            sum += __shfl_xor_sync(0xffffffffu, sum, 1);
            sum += __shfl_xor_sync(0xffffffffu, sum, 2);
            if (sub == 0) {
                float sc = __expf(m0 - mx);
                rowl[r] = rowl[r] * sc + sum;
                rowm[r] = mx;
                rowsc[r] = sc;
            }
        }
        __syncthreads();

        // ---- write fp16 P (aliased) + in-register O rescale ----
        for (int c0 = 0; c0 < 16; c0++)
            Ph[r * 72 + sub * 16 + c0] = __float2half(pv[c0]);
        {
            float s0 = rowsc[fr0], s1 = rowsc[fr1];
            for (int nt = 0; nt < 4; nt++) {
                ofr[nt].x[0] *= s0; ofr[nt].x[1] *= s0;
                ofr[nt].x[4] *= s0; ofr[nt].x[5] *= s0;
                ofr[nt].x[2] *= s1; ofr[nt].x[3] *= s1;
                ofr[nt].x[6] *= s1; ofr[nt].x[7] *= s1;
            }
        }
        __syncthreads();

        // ---- O += P @ V : each warp 16 rows x 64 cols ----
        {
            wmma::fragment<wmma::matrix_a, 16, 16, 16, __half, wmma::row_major> af[4];
            for (int kk = 0; kk < 4; kk++)
                wmma::load_matrix_sync(af[kk], Ph + wq * 16 * 72 + kk * 16, 72);
            for (int nt = 0; nt < 4; nt++) {
                int col0 = wc * 64 + nt * 16;
                for (int kk = 0; kk < 4; kk++) {
                    wmma::fragment<wmma::matrix_b, 16, 16, 16, __half, wmma::row_major> bf;
                    wmma::load_matrix_sync(bf, Vs + kk * 16 * 136 + col0, 136);
                    wmma::mma_sync(ofr[nt], af[kk], bf, ofr[nt]);
                }
            }
        }
    }
    __syncthreads();

    // ---- final in-register normalize ----
    {
        float l0 = 1.f / rowl[fr0], l1 = 1.f / rowl[fr1];
        for (int nt = 0; nt < 4; nt++) {
            ofr[nt].x[0] *= l0; ofr[nt].x[1] *= l0;
            ofr[nt].x[4] *= l0; ofr[nt].x[5] *= l0;
            ofr[nt].x[2] *= l1; ofr[nt].x[3] *= l1;
            ofr[nt].x[6] *= l1; ofr[nt].x[7] *= l1;
        }
    }
    // ---- two-phase output through Ps (128x72 f32 holds 64 cols) ----
    for (int ph = 0; ph < 2; ph++) {
        if (wc == ph)
            for (int nt = 0; nt < 4; nt++)
                wmma::store_matrix_sync(Ps + (wq * 16) * 72 + nt * 16, ofr[nt],
                                        72, wmma::mem_row_major);
        __syncthreads();
        for (int i = tid; i < 128 * 8; i += 512) {
            int r = i >> 3, ch = i & 7;
            __half tmp[8];
            for (int j = 0; j < 8; j++)
                tmp[j] = __float2half(Ps[r * 72 + ch * 8 + j]);
            *(uint4*)(Om + (size_t)(b * SEQ + q0 + r) * (NH * HD) + h * HD + ph * 64 + ch * 8) = *(uint4*)tmp;
        }
        __syncthreads();
    }
}

// ---------------- MoD compaction (single block, deterministic) ------------
__global__ void compact_kernel(const int* __restrict__ mask,
                               const float* __restrict__ scores) {
    __shared__ int ssum[256];
    __shared__ int base;
    const int t = threadIdx.x;
    if (t == 0) base = 0;
    __syncthreads();
    for (int start = 0; start < TOK; start += 256) {
        int i = start + t;
        int f = (mask[i] != 0) ? 1 : 0;
        g_scale[i] = 0.5f + (scores[i] - 0.5f) * 0.7f;
        ssum[t] = f;
        __syncthreads();
        for (int off = 1; off < 256; off <<= 1) {
            int v = (t >= off) ? ssum[t - off] : 0;
            __syncthreads();
            ssum[t] += v;
            __syncthreads();
        }
        if (f) g_idx[base + ssum[t] - 1] = i;
        __syncthreads();
        if (t == 0) base += ssum[255];
        __syncthreads();
    }
    if (t == 0) g_nsel = base;
}

// ---------------- residual copy to output ---------------------------------
__global__ void copy_kernel(float* __restrict__ dst, const float* __restrict__ src) {
    int i = blockIdx.x * blockDim.x + threadIdx.x;
    if (i < TOK * DIM / 4)
        ((float4*)dst)[i] = ((const float4*)src)[i];
}

// ---------------- driver ---------------------------------------------------
extern "C" void kernel_launch(void* const* d_in, const int* in_sizes, int n_in,
                              void* d_out, int out_size) {
    const float* hidden = (const float*)d_in[0];
    const int* mask = (const int*)d_in[1];
    const float* tscore = (const float*)d_in[2];
    const float* ln1 = (const float*)d_in[3];
    const float* ln2 = (const float*)d_in[4];
    const float* q_w = (const float*)d_in[5];
    const float* k_w = (const float*)d_in[6];
    const float* v_w = (const float*)d_in[7];
    const float* o_w = (const float*)d_in[8];
    const float* gate_w = (const float*)d_in[9];
    const float* up_w = (const float*)d_in[10];
    const float* down_w = (const float*)d_in[11];
    float* out = (float*)d_out;

    void* p;
    cudaGetSymbolAddress(&p, g_h);     float* h = (float*)p;
    cudaGetSymbolAddress(&p, g_rope);  float2* rtab = (float2*)p;
    __half *xnh, *qkvh, *ah, *hnh, *acth;
    __half *qkvw, *owh, *guw, *dwh;
    cudaGetSymbolAddress(&p, g_xnh);   xnh = (__half*)p;
    cudaGetSymbolAddress(&p, g_qkvh);  qkvh = (__half*)p;
    cudaGetSymbolAddress(&p, g_ah);    ah = (__half*)p;
    cudaGetSymbolAddress(&p, g_hnh);   hnh = (__half*)p;
    cudaGetSymbolAddress(&p, g_acth);  acth = (__half*)p;
    cudaGetSymbolAddress(&p, g_qkvw);  qkvw = (__half*)p;
    cudaGetSymbolAddress(&p, g_owh);   owh = (__half*)p;
    cudaGetSymbolAddress(&p, g_guw);   guw = (__half*)p;
    cudaGetSymbolAddress(&p, g_dwh);   dwh = (__half*)p;

    cudaFuncSetAttribute(fp16_gemm, cudaFuncAttributeMaxDynamicSharedMemorySize,
                         GEMM_SMEM_BYTES);
    cudaFuncSetAttribute(attn_wmma, cudaFuncAttributeMaxDynamicSharedMemorySize,
                         ATTN_SMEM_BYTES);

    dim3 blk(256);
    const int smg = GEMM_SMEM_BYTES;

    // 0. convert weights to fp16 (qkv concat; gate/up row-interleaved)
    cvt_kernel<<<(DIM * DIM / 4 + 255) / 256, blk>>>(q_w, qkvw, DIM * DIM / 4);
    cvt_kernel<<<(NKVH * HD * DIM / 4 + 255) / 256, blk>>>(k_w, qkvw + (size_t)DIM * DIM, NKVH * HD * DIM / 4);
    cvt_kernel<<<(NKVH * HD * DIM / 4 + 255) / 256, blk>>>(v_w, qkvw + (size_t)(DIM + NKVH * HD) * DIM, NKVH * HD * DIM / 4);
    cvt_kernel<<<(DIM * DIM / 4 + 255) / 256, blk>>>(o_w, owh, DIM * DIM / 4);
    cvt_ilv_kernel<<<(FF * DIM / 4 + 255) / 256, blk>>>(gate_w, guw, FF * DIM / 4, 0);
    cvt_ilv_kernel<<<(FF * DIM / 4 + 255) / 256, blk>>>(up_w, guw, FF * DIM / 4, 1);
    cvt_kernel<<<(DIM * FF / 4 + 255) / 256, blk>>>(down_w, dwh, DIM * FF / 4);
    // rope table
    rope_table_kernel<<<(SEQ * 64 + 255) / 256, blk>>>(rtab);

    // 1. ln1 -> fp16
    rmsnorm_half_kernel<<<TOK, blk>>>(hidden, ln1, xnh);
    // 2. fused qkv projection
    fp16_gemm<<<dim3(QKVN / GBN, TOK / GBM), blk, smg>>>(xnh, qkvw, (float*)0, qkvh, (const float*)0, TOK, QKVN, DIM, 0, 0, 0, 0);
    // 3. rope (Q + K heads) via table
    rope_apply_kernel<<<(TOK * (NH + NKVH) * 64 + 255) / 256, blk>>>(qkvh, rtab);
    // 4. attention (128-row q-tiles) -> ah
    attn_wmma<<<dim3(SEQ / 128, NH, BATCH), dim3(512), ATTN_SMEM_BYTES>>>(qkvh, ah);
    // 5. o-proj + residual -> h fp32
    fp16_gemm<<<dim3(DIM / GBN, TOK / GBM), blk, smg>>>(ah, owh, h, (__half*)0, hidden, TOK, DIM, NH * HD, 0, 0, 0, 0);
    // 6. ln2 -> fp16
    rmsnorm_half_kernel<<<TOK, blk>>>(h, ln2, hnh);
    // 7. MoD compaction
    compact_kernel<<<1, blk>>>(mask, tscore);
    // 8. fused gate|up GEMM with silu epilogue -> acth directly
    fp16_gemm<<<dim3(GUN / GBN, TOK / GBM), blk, smg>>>(hnh, guw, (float*)0, acth, (const float*)0, TOK, GUN, DIM, 1, 0, 1, 1);
    // 9. out = h
    copy_kernel<<<(TOK * DIM / 4 + 255) / 256, blk>>>(out, h);
    // 10. down-proj, scatter-add with per-token MoD scale
    fp16_gemm<<<dim3(DIM / GBN, TOK / GBM), blk, smg>>>(acth, dwh, out, (__half*)0, (const float*)0, TOK, DIM, FF, 0, 1, 1, 0);
}

// round 17
// speedup vs baseline: 1.0126x; 1.0126x over previous
#include <cuda_runtime.h>
#include <cuda_fp16.h>
#include <cuda_pipeline.h>
#include <mma.h>
#include <stdint.h>
#include <math.h>

using namespace nvcuda;

#define TOK 4096
#define DIM 2048
#define NH 16
#define NKVH 4
#define HD 128
#define FF 7168
#define SEQ 2048
#define BATCH 2
#define QKVN 3072
#define GUN (2 * FF)
#define ROPE_COLS 2560   // Q (2048) + K (512) head cols get rope

#define GBM 128
#define GBN 128
#define GBK 64
#define GLD 72
#define TILE_ELEMS (GBM * GLD)
#define STAGE_BYTES (2 * TILE_ELEMS * 2)
#define GEMM_SMEM_BYTES (2 * STAGE_BYTES)

// attention smem (R15 config): Qs/Ks/Vs fp16 [64][136], Ps f32 [64][72]
// (fp16 P aliased), rowm/rowl/rowsc. O in registers.
#define ATTN_SMEM_BYTES (3 * 64 * 136 * 2 + 64 * 72 * 4 + 3 * 64 * 4)

// ---------------- scratch (static device globals; no allocation allowed) ---
__device__ float g_h[TOK * DIM];
__device__ int   g_idx[TOK];
__device__ float g_scale[TOK];
__device__ int   g_nsel;
__device__ float2 g_rope[SEQ * 64];

// fp16 activation planes
__device__ __half g_xnh[TOK * DIM];
__device__ __half g_qkvh[TOK * QKVN];
__device__ __half g_ah[TOK * DIM];
__device__ __half g_hnh[TOK * DIM];
__device__ __half g_acth[TOK * FF];
// fp16 weight planes
__device__ __half g_qkvw[QKVN * DIM];
__device__ __half g_owh[DIM * DIM];
__device__ __half g_guw[GUN * DIM];   // interleaved: row 2i = gate i, 2i+1 = up i
__device__ __half g_dwh[DIM * FF];

// ---------------- fp32 -> fp16 convert (16B/thread, proven) ----------------
__global__ void cvt_kernel(const float* __restrict__ src,
                           __half* __restrict__ dst, int n4) {
    int i = blockIdx.x * blockDim.x + threadIdx.x;
    if (i >= n4) return;
    float4 v = ((const float4*)src)[i];
    __half2* hp = (__half2*)dst + i * 2;
    hp[0] = __floats2half2_rn(v.x, v.y);
    hp[1] = __floats2half2_rn(v.z, v.w);
}

// ---------------- fp32 -> fp16 convert with row interleave 2r+off ----------
__global__ void cvt_ilv_kernel(const float* __restrict__ src,
                               __half* __restrict__ dst, int n4, int off) {
    int i = blockIdx.x * blockDim.x + threadIdx.x;
    if (i >= n4) return;
    float4 v = ((const float4*)src)[i];
    int idx = i * 4;
    int row = idx / DIM;
    int col = idx - row * DIM;
    __half2* hp = (__half2*)(dst + ((size_t)(2 * row + off)) * DIM + col);
    hp[0] = __floats2half2_rn(v.x, v.y);
    hp[1] = __floats2half2_rn(v.z, v.w);
}

// ---------------- fp16 GEMM: C[M,N] = A[M,K] @ W[N,K]^T --------------------
// ropeN > 0: N-tiles with bn < ropeN get in-epilogue RoPE rotation
// (GBN == HD: each N-tile is one head; smem C-tile holds both halves).
__global__ __launch_bounds__(256)
void fp16_gemm(const __half* __restrict__ Ah, const __half* __restrict__ Wh,
               float* __restrict__ C, __half* __restrict__ Ch,
               const float* __restrict__ Res,
               int M, int N, int K, int gather, int scatter, int dynm,
               int silu, int ropeN) {
    const int Mreal = dynm ? g_nsel : M;
    const int bm = blockIdx.y * GBM;
    if (bm >= Mreal) return;
    const int bn = blockIdx.x * GBN;

    extern __shared__ char smraw[];

    const int tid = threadIdx.x;
    const int warp = tid >> 5;
    const int wm = (warp >> 1) * 32;
    const int wn = (warp & 1) * 64;

    const int cc = tid & 7;
    int lrow[4], arowg[4], wrowg[4];
    bool avalid[4];
    for (int t = 0; t < 4; t++) {
        int row = (tid >> 3) + t * 32;
        lrow[t] = row;
        int am = bm + row;
        avalid[t] = (am < Mreal);
        arowg[t] = avalid[t] ? (gather ? g_idx[am] : am) : 0;
        wrowg[t] = bn + row;
    }

    wmma::fragment<wmma::accumulator, 16, 16, 16, float> acc[2][4];
    for (int mt = 0; mt < 2; mt++)
        for (int nt = 0; nt < 4; nt++)
            wmma::fill_fragment(acc[mt][nt], 0.0f);

    const int nchunks = K / GBK;
    const uint4 zz = make_uint4(0u, 0u, 0u, 0u);

    for (int c = 0; c < nchunks + 1; c++) {
        if (c < nchunks) {
            char* sb = smraw + (c & 1) * STAGE_BYTES;
            __half* sA = (__half*)sb;
            __half* sW = sA + TILE_ELEMS;
            int k0 = c * GBK;
            for (int t = 0; t < 4; t++) {
                int so = lrow[t] * GLD + cc * 8;
                if (avalid[t]) {
                    size_t go = (size_t)arowg[t] * K + k0 + cc * 8;
                    __pipeline_memcpy_async(sA + so, Ah + go, 16);
                } else {
                    *(uint4*)(sA + so) = zz;
                }
                size_t wo = (size_t)wrowg[t] * K + k0 + cc * 8;
                __pipeline_memcpy_async(sW + so, Wh + wo, 16);
            }
            __pipeline_commit();
        }
        if (c > 0) {
            __pipeline_wait_prior(c < nchunks ? 1 : 0);
            __syncthreads();
            char* sb = smraw + ((c - 1) & 1) * STAGE_BYTES;
            const __half* sA = (const __half*)sb;
            const __half* sW = sA + TILE_ELEMS;
            for (int kc = 0; kc < GBK; kc += 16) {
                wmma::fragment<wmma::matrix_a, 16, 16, 16, __half, wmma::row_major> af[2];
                wmma::fragment<wmma::matrix_b, 16, 16, 16, __half, wmma::col_major> bf[4];
                for (int mt = 0; mt < 2; mt++)
                    wmma::load_matrix_sync(af[mt], sA + (wm + mt * 16) * GLD + kc, GLD);
                for (int nt = 0; nt < 4; nt++)
                    wmma::load_matrix_sync(bf[nt], sW + (wn + nt * 16) * GLD + kc, GLD);
                for (int mt = 0; mt < 2; mt++)
                    for (int nt = 0; nt < 4; nt++)
                        wmma::mma_sync(acc[mt][nt], af[mt], bf[nt], acc[mt][nt]);
            }
            __syncthreads();
        }
    }

    float* Cs = (float*)smraw;     // 128 x 136
    for (int mt = 0; mt < 2; mt++)
        for (int nt = 0; nt < 4; nt++)
            wmma::store_matrix_sync(Cs + (wm + mt * 16) * 136 + wn + nt * 16,
                                    acc[mt][nt], 136, wmma::mem_row_major);
    __syncthreads();

    {
        int r = tid >> 1;
        int c0 = (tid & 1) * 64;
        int row = bm + r;
        if (row < Mreal) {
            const float* cr = Cs + r * 136 + c0;
            if (Ch) {
                if (silu) {
                    size_t off = (size_t)row * (N / 2) + (bn + c0) / 2;
                    for (int j0 = 0; j0 < 64; j0 += 16) {
                        __half tmp[8];
                        for (int j = 0; j < 8; j++) {
                            float g = cr[j0 + 2 * j];
                            float u = cr[j0 + 2 * j + 1];
                            tmp[j] = __float2half((g / (1.f + __expf(-g))) * u);
                        }
                        *(uint4*)(Ch + off + j0 / 2) = *(uint4*)tmp;
                    }
                } else if (bn < ropeN) {
                    // in-epilogue RoPE: this half c0, other half at +-64
                    const float2* rt = g_rope + (size_t)(row % SEQ) * 64;
                    const float* oth = cr + (c0 ? -64 : 64);
                    float sgn = c0 ? 1.f : -1.f;
                    size_t off = (size_t)row * N + bn + c0;
                    for (int j0 = 0; j0 < 64; j0 += 8) {
                        __half tmp[8];
                        for (int j = 0; j < 8; j++) {
                            float2 cs = rt[j0 + j];
                            tmp[j] = __float2half(cr[j0 + j] * cs.x + sgn * oth[j0 + j] * cs.y);
                        }
                        *(uint4*)(Ch + off + j0) = *(uint4*)tmp;
                    }
                } else {
                    size_t off = (size_t)row * N + bn + c0;
                    for (int j0 = 0; j0 < 64; j0 += 8) {
                        __half tmp[8];
                        for (int j = 0; j < 8; j++) tmp[j] = __float2half(cr[j0 + j]);
                        *(uint4*)(Ch + off + j0) = *(uint4*)tmp;
                    }
                }
            } else {
                int crow = scatter ? g_idx[row] : row;
                size_t off = (size_t)crow * N + bn + c0;
                if (scatter) {
                    float rs = g_scale[crow];
                    for (int j = 0; j < 64; j++) C[off + j] += rs * cr[j];
                } else if (Res) {
                    for (int j = 0; j < 64; j++) C[off + j] = Res[off + j] + cr[j];
                } else {
                    for (int j = 0; j < 64; j++) C[off + j] = cr[j];
                }
            }
        }
    }
}

// ---------------- RMSNorm (writes fp16 plane) -------------------------------
__global__ void rmsnorm_half_kernel(const float* __restrict__ x,
                                    const float* __restrict__ w,
                                    __half* __restrict__ oh) {
    const int row = blockIdx.x;
    const float* xr = x + (size_t)row * DIM;
    float ss = 0.f;
    for (int i = threadIdx.x; i < DIM; i += 256) {
        float v = xr[i];
        ss += v * v;
    }
    __shared__ float red[256];
    red[threadIdx.x] = ss;
    __syncthreads();
    for (int off = 128; off > 0; off >>= 1) {
        if (threadIdx.x < off) red[threadIdx.x] += red[threadIdx.x + off];
        __syncthreads();
    }
    float rs = rsqrtf(red[0] / (float)DIM + 1e-5f);
    for (int i = threadIdx.x; i < DIM; i += 256)
        oh[(size_t)row * DIM + i] = __float2half(xr[i] * rs * w[i]);
}

// ---------------- RoPE table (once per call; tiny) --------------------------
__global__ void rope_table_kernel(float2* __restrict__ tab) {
    int i = blockIdx.x * blockDim.x + threadIdx.x;
    if (i >= SEQ * 64) return;
    int pos = i >> 6, half = i & 63;
    float inv = expf(-logf(10000.f) * (float)half * (1.f / 64.f));
    float ang = (float)pos * inv;
    tab[i] = make_float2(cosf(ang), sinf(ang));
}

// ---------------- WMMA flash attention (R15 config: 64-row q-tiles) ---------
__global__ __launch_bounds__(256)
void attn_wmma(const __half* __restrict__ QKV, __half* __restrict__ Om) {
    extern __shared__ char smb[];
    __half* Qs = (__half*)smb;             // [64][136]
    __half* Ks = Qs + 64 * 136;            // [64][136]
    __half* Vs = Ks + 64 * 136;            // [64][136]
    float*  Ps = (float*)(Vs + 64 * 136);  // [64][72] f32; fp16 P aliased
    __half* Ph = (__half*)Ps;
    float* rowm = Ps + 64 * 72;
    float* rowl = rowm + 64;
    float* rowsc = rowl + 64;

    const int tid = threadIdx.x;
    const int warp = tid >> 5;
    const int lane = tid & 31;
    const int wq = warp >> 1;
    const int wc = warp & 1;
    const int qt = gridDim.x - 1 - blockIdx.x;   // heavy tiles first
    const int h = blockIdx.y, b = blockIdx.z;
    const int kvh = h / (NH / NKVH);
    const int q0 = qt * 64;

    for (int i = tid; i < 64 * 16; i += 256) {
        int r = i >> 4, ch = i & 15;
        *(uint4*)(Qs + r * 136 + ch * 8) =
            *(const uint4*)(QKV + (size_t)(b * SEQ + q0 + r) * QKVN + h * HD + ch * 8);
    }
    if (tid < 64) { rowm[tid] = -1e30f; rowl[tid] = 0.f; }

    const float qk_scale = 0.08838834764831845f;

    wmma::fragment<wmma::accumulator, 16, 16, 16, float> ofr[4];
    for (int nt = 0; nt < 4; nt++) wmma::fill_fragment(ofr[nt], 0.0f);

    const int fr0 = wq * 16 + (lane >> 2);
    const int fr1 = fr0 + 8;

    for (int kt = 0; kt <= qt; kt++) {
        __syncthreads();
        for (int i = tid; i < 64 * 16; i += 256) {
            int r = i >> 4, ch = i & 15;
            size_t base = (size_t)(b * SEQ + kt * 64 + r) * QKVN + kvh * HD + ch * 8;
            *(uint4*)(Ks + r * 136 + ch * 8) = *(const uint4*)(QKV + base + DIM);
            *(uint4*)(Vs + r * 136 + ch * 8) = *(const uint4*)(QKV + base + DIM + NKVH * HD);
        }
        __syncthreads();

        {
            wmma::fragment<wmma::accumulator, 16, 16, 16, float> sfr[2];
            wmma::fill_fragment(sfr[0], 0.0f);
            wmma::fill_fragment(sfr[1], 0.0f);
            for (int kd = 0; kd < 128; kd += 16) {
                wmma::fragment<wmma::matrix_a, 16, 16, 16, __half, wmma::row_major> af;
                wmma::load_matrix_sync(af, Qs + wq * 16 * 136 + kd, 136);
                for (int nt = 0; nt < 2; nt++) {
                    wmma::fragment<wmma::matrix_b, 16, 16, 16, __half, wmma::col_major> bf;
                    wmma::load_matrix_sync(bf, Ks + (wc * 32 + nt * 16) * 136 + kd, 136);
                    wmma::mma_sync(sfr[nt], af, bf, sfr[nt]);
                }
            }
            for (int nt = 0; nt < 2; nt++)
                wmma::store_matrix_sync(Ps + wq * 16 * 72 + wc * 32 + nt * 16,
                                        sfr[nt], 72, wmma::mem_row_major);
        }
        __syncthreads();

        float pv[16];
        int r = tid >> 2, sub = tid & 3;
        {
            int gq = q0 + r;
            float m0 = rowm[r];
            float vals[16];
            float mx = m0;
            for (int c0 = 0; c0 < 16; c0++) {
                int c = sub * 16 + c0;
                int gk = kt * 64 + c;
                float v = Ps[r * 72 + c] * qk_scale;
                if (gk > gq) v = -1e30f;
                vals[c0] = v;
                mx = fmaxf(mx, v);
            }
            mx = fmaxf(mx, __shfl_xor_sync(0xffffffffu, mx, 1));
            mx = fmaxf(mx, __shfl_xor_sync(0xffffffffu, mx, 2));
            float sum = 0.f;
            for (int c0 = 0; c0 < 16; c0++) {
                pv[c0] = __expf(vals[c0] - mx);
                sum += pv[c0];
            }
            sum += __shfl_xor_sync(0xffffffffu, sum, 1);
            sum += __shfl_xor_sync(0xffffffffu, sum, 2);
            if (sub == 0) {
                float sc = __expf(m0 - mx);
                rowl[r] = rowl[r] * sc + sum;
                rowm[r] = mx;
                rowsc[r] = sc;
            }
        }
        __syncthreads();

        for (int c0 = 0; c0 < 16; c0++)
            Ph[r * 72 + sub * 16 + c0] = __float2half(pv[c0]);
        {
            float s0 = rowsc[fr0], s1 = rowsc[fr1];
            for (int nt = 0; nt < 4; nt++) {
                ofr[nt].x[0] *= s0; ofr[nt].x[1] *= s0;
                ofr[nt].x[4] *= s0; ofr[nt].x[5] *= s0;
                ofr[nt].x[2] *= s1; ofr[nt].x[3] *= s1;
                ofr[nt].x[6] *= s1; ofr[nt].x[7] *= s1;
            }
        }
        __syncthreads();

        {
            wmma::fragment<wmma::matrix_a, 16, 16, 16, __half, wmma::row_major> af[4];
            for (int kk = 0; kk < 4; kk++)
                wmma::load_matrix_sync(af[kk], Ph + wq * 16 * 72 + kk * 16, 72);
            for (int nt = 0; nt < 4; nt++) {
                int col0 = wc * 64 + nt * 16;
                for (int kk = 0; kk < 4; kk++) {
                    wmma::fragment<wmma::matrix_b, 16, 16, 16, __half, wmma::row_major> bf;
                    wmma::load_matrix_sync(bf, Vs + kk * 16 * 136 + col0, 136);
                    wmma::mma_sync(ofr[nt], af[kk], bf, ofr[nt]);
                }
            }
        }
    }
    __syncthreads();

    {
        float l0 = 1.f / rowl[fr0], l1 = 1.f / rowl[fr1];
        for (int nt = 0; nt < 4; nt++) {
            ofr[nt].x[0] *= l0; ofr[nt].x[1] *= l0;
            ofr[nt].x[4] *= l0; ofr[nt].x[5] *= l0;
            ofr[nt].x[2] *= l1; ofr[nt].x[3] *= l1;
            ofr[nt].x[6] *= l1; ofr[nt].x[7] *= l1;
        }
    }
    for (int ph = 0; ph < 2; ph++) {
        if (wc == ph)
            for (int nt = 0; nt < 4; nt++)
                wmma::store_matrix_sync(Ps + (wq * 16) * 72 + nt * 16, ofr[nt],
                                        72, wmma::mem_row_major);
        __syncthreads();
        for (int i = tid; i < 64 * 8; i += 256) {
            int r = i >> 3, ch = i & 7;
            __half tmp[8];
            for (int j = 0; j < 8; j++)
                tmp[j] = __float2half(Ps[r * 72 + ch * 8 + j]);
            *(uint4*)(Om + (size_t)(b * SEQ + q0 + r) * (NH * HD) + h * HD + ph * 64 + ch * 8) = *(uint4*)tmp;
        }
        __syncthreads();
    }
}

// ---------------- MoD compaction (single block, deterministic) ------------
__global__ void compact_kernel(const int* __restrict__ mask,
                               const float* __restrict__ scores) {
    __shared__ int ssum[256];
    __shared__ int base;
    const int t = threadIdx.x;
    if (t == 0) base = 0;
    __syncthreads();
    for (int start = 0; start < TOK; start += 256) {
        int i = start + t;
        int f = (mask[i] != 0) ? 1 : 0;
        g_scale[i] = 0.5f + (scores[i] - 0.5f) * 0.7f;
        ssum[t] = f;
        __syncthreads();
        for (int off = 1; off < 256; off <<= 1) {
            int v = (t >= off) ? ssum[t - off] : 0;
            __syncthreads();
            ssum[t] += v;
            __syncthreads();
        }
        if (f) g_idx[base + ssum[t] - 1] = i;
        __syncthreads();
        if (t == 0) base += ssum[255];
        __syncthreads();
    }
    if (t == 0) g_nsel = base;
}

// ---------------- residual copy to output ---------------------------------
__global__ void copy_kernel(float* __restrict__ dst, const float* __restrict__ src) {
    int i = blockIdx.x * blockDim.x + threadIdx.x;
    if (i < TOK * DIM / 4)
        ((float4*)dst)[i] = ((const float4*)src)[i];
}

// ---------------- driver ---------------------------------------------------
extern "C" void kernel_launch(void* const* d_in, const int* in_sizes, int n_in,
                              void* d_out, int out_size) {
    const float* hidden = (const float*)d_in[0];
    const int* mask = (const int*)d_in[1];
    const float* tscore = (const float*)d_in[2];
    const float* ln1 = (const float*)d_in[3];
    const float* ln2 = (const float*)d_in[4];
    const float* q_w = (const float*)d_in[5];
    const float* k_w = (const float*)d_in[6];
    const float* v_w = (const float*)d_in[7];
    const float* o_w = (const float*)d_in[8];
    const float* gate_w = (const float*)d_in[9];
    const float* up_w = (const float*)d_in[10];
    const float* down_w = (const float*)d_in[11];
    float* out = (float*)d_out;

    void* p;
    cudaGetSymbolAddress(&p, g_h);     float* h = (float*)p;
    cudaGetSymbolAddress(&p, g_rope);  float2* rtab = (float2*)p;
    __half *xnh, *qkvh, *ah, *hnh, *acth;
    __half *qkvw, *owh, *guw, *dwh;
    cudaGetSymbolAddress(&p, g_xnh);   xnh = (__half*)p;
    cudaGetSymbolAddress(&p, g_qkvh);  qkvh = (__half*)p;
    cudaGetSymbolAddress(&p, g_ah);    ah = (__half*)p;
    cudaGetSymbolAddress(&p, g_hnh);   hnh = (__half*)p;
    cudaGetSymbolAddress(&p, g_acth);  acth = (__half*)p;
    cudaGetSymbolAddress(&p, g_qkvw);  qkvw = (__half*)p;
    cudaGetSymbolAddress(&p, g_owh);   owh = (__half*)p;
    cudaGetSymbolAddress(&p, g_guw);   guw = (__half*)p;
    cudaGetSymbolAddress(&p, g_dwh);   dwh = (__half*)p;

    cudaFuncSetAttribute(fp16_gemm, cudaFuncAttributeMaxDynamicSharedMemorySize,
                         GEMM_SMEM_BYTES);
    cudaFuncSetAttribute(attn_wmma, cudaFuncAttributeMaxDynamicSharedMemorySize,
                         ATTN_SMEM_BYTES);

    dim3 blk(256);
    const int smg = GEMM_SMEM_BYTES;

    // 0. convert weights to fp16 (qkv concat; gate/up row-interleaved)
    cvt_kernel<<<(DIM * DIM / 4 + 255) / 256, blk>>>(q_w, qkvw, DIM * DIM / 4);
    cvt_kernel<<<(NKVH * HD * DIM / 4 + 255) / 256, blk>>>(k_w, qkvw + (size_t)DIM * DIM, NKVH * HD * DIM / 4);
    cvt_kernel<<<(NKVH * HD * DIM / 4 + 255) / 256, blk>>>(v_w, qkvw + (size_t)(DIM + NKVH * HD) * DIM, NKVH * HD * DIM / 4);
    cvt_kernel<<<(DIM * DIM / 4 + 255) / 256, blk>>>(o_w, owh, DIM * DIM / 4);
    cvt_ilv_kernel<<<(FF * DIM / 4 + 255) / 256, blk>>>(gate_w, guw, FF * DIM / 4, 0);
    cvt_ilv_kernel<<<(FF * DIM / 4 + 255) / 256, blk>>>(up_w, guw, FF * DIM / 4, 1);
    cvt_kernel<<<(DIM * FF / 4 + 255) / 256, blk>>>(down_w, dwh, DIM * FF / 4);
    // rope table
    rope_table_kernel<<<(SEQ * 64 + 255) / 256, blk>>>(rtab);

    // 1. ln1 -> fp16
    rmsnorm_half_kernel<<<TOK, blk>>>(hidden, ln1, xnh);
    // 2. fused qkv projection with in-epilogue RoPE on Q/K head tiles
    fp16_gemm<<<dim3(QKVN / GBN, TOK / GBM), blk, smg>>>(xnh, qkvw, (float*)0, qkvh, (const float*)0, TOK, QKVN, DIM, 0, 0, 0, 0, ROPE_COLS);
    // 3. attention -> ah
    attn_wmma<<<dim3(SEQ / 64, NH, BATCH), blk, ATTN_SMEM_BYTES>>>(qkvh, ah);
    // 4. o-proj + residual -> h fp32
    fp16_gemm<<<dim3(DIM / GBN, TOK / GBM), blk, smg>>>(ah, owh, h, (__half*)0, hidden, TOK, DIM, NH * HD, 0, 0, 0, 0, 0);
    // 5. ln2 -> fp16
    rmsnorm_half_kernel<<<TOK, blk>>>(h, ln2, hnh);
    // 6. MoD compaction
    compact_kernel<<<1, blk>>>(mask, tscore);
    // 7. fused gate|up GEMM with silu epilogue -> acth directly
    fp16_gemm<<<dim3(GUN / GBN, TOK / GBM), blk, smg>>>(hnh, guw, (float*)0, acth, (const float*)0, TOK, GUN, DIM, 1, 0, 1, 1, 0);
    // 8. out = h
    copy_kernel<<<(TOK * DIM / 4 + 255) / 256, blk>>>(out, h);
    // 9. down-proj, scatter-add with per-token MoD scale
    fp16_gemm<<<dim3(DIM / GBN, TOK / GBM), blk, smg>>>(acth, dwh, out, (__half*)0, (const float*)0, TOK, DIM, FF, 0, 1, 1, 0, 0);
}